// round 2
// baseline (speedup 1.0000x reference)
#include <cuda_runtime.h>
#include <math.h>

// MSEObserver: 1600-candidate quantization range search over a 1024x4096 fp32 tensor.
// Pipeline: init -> global min/max -> per-candidate params -> brute-force scoring
// (grid = 32 element chunks x 100 candidate groups, 16 candidates/block in regs)
// -> deterministic partial reduce -> sequential scan selection.

#define NCAND   1600
#define NI      100
#define NZ      16
#define NCHUNK  32
#define TPB     256
#define CPG     16     // candidates per group (per block)
#define NGROUP  100
#define MAGIC   12582912.0f   // 1.5 * 2^23 : RNE rounding trick for |v| < 2^22

__device__ unsigned int g_minmax_bits[2];             // order-encoded min/max
__device__ float4 g_params[NCAND];                    // {scale, 1/scale, -zp, 15-zp}
__device__ float2 g_cand_mm[NCAND];                   // {new_min, new_max}
__device__ float  g_partials[NGROUP * NCHUNK * CPG];  // per (group, chunk, cand)

__device__ __forceinline__ unsigned int enc_ord(float f) {
    unsigned int u = __float_as_uint(f);
    return (u & 0x80000000u) ? ~u : (u | 0x80000000u);
}
__device__ __forceinline__ float dec_ord(unsigned int u) {
    return (u & 0x80000000u) ? __uint_as_float(u ^ 0x80000000u)
                             : __uint_as_float(~u);
}

__global__ void k_init() {
    g_minmax_bits[0] = 0xFFFFFFFFu;  // encoded +inf (min identity)
    g_minmax_bits[1] = 0x00000000u;  // encoded -inf (max identity)
}

__global__ void k_minmax(const float4* __restrict__ x4, int n4) {
    float mn =  3.402823466e+38f;
    float mx = -3.402823466e+38f;
    for (int i = blockIdx.x * blockDim.x + threadIdx.x; i < n4;
         i += gridDim.x * blockDim.x) {
        float4 v = x4[i];
        mn = fminf(mn, fminf(fminf(v.x, v.y), fminf(v.z, v.w)));
        mx = fmaxf(mx, fmaxf(fmaxf(v.x, v.y), fmaxf(v.z, v.w)));
    }
    #pragma unroll
    for (int o = 16; o; o >>= 1) {
        mn = fminf(mn, __shfl_down_sync(0xFFFFFFFFu, mn, o));
        mx = fmaxf(mx, __shfl_down_sync(0xFFFFFFFFu, mx, o));
    }
    __shared__ float smn[TPB / 32], smx[TPB / 32];
    int w = threadIdx.x >> 5;
    if ((threadIdx.x & 31) == 0) { smn[w] = mn; smx[w] = mx; }
    __syncthreads();
    if (threadIdx.x == 0) {
        for (int ww = 1; ww < TPB / 32; ww++) {
            mn = fminf(mn, smn[ww]);
            mx = fmaxf(mx, smx[ww]);
        }
        atomicMin(&g_minmax_bits[0], enc_ord(mn));
        atomicMax(&g_minmax_bits[1], enc_ord(mx));
    }
}

// Mirror the reference parameter math op-for-op in fp32 (no contraction).
__global__ void k_params() {
    int k = blockIdx.x * blockDim.x + threadIdx.x;
    if (k >= NCAND) return;
    float x_min = dec_ord(g_minmax_bits[0]);
    float x_max = dec_ord(g_minmax_bits[1]);
    float xrange = __fsub_rn(x_max, x_min);

    int ii = k / NZ;            // 0..99  -> i = ii+1
    int z  = k % NZ;            // 0..15
    float fi = (float)(ii + 1);
    float zf = (float)z;

    float tmp_max   = __fmul_rn(__fdiv_rn(xrange, 100.0f), fi);
    float tmp_delta = __fdiv_rn(tmp_max, 15.0f);
    float p         = __fmul_rn(zf, tmp_delta);
    float new_min   = fmaxf(-p, x_min);
    float new_max   = fminf(__fsub_rn(tmp_max, p), x_max);
    float min_neg   = fminf(new_min, 0.0f);
    float max_pos   = fmaxf(new_max, 0.0f);
    float scale     = fmaxf(__fdiv_rn(__fsub_rn(max_pos, min_neg), 15.0f),
                            1.1920929e-07f);
    float zp = fminf(fmaxf(__fsub_rn(0.0f, rintf(__fdiv_rn(min_neg, scale))),
                           0.0f), 15.0f);

    g_params[k]  = make_float4(scale, __frcp_rn(scale), -zp, 15.0f - zp);
    g_cand_mm[k] = make_float2(new_min, new_max);
}

// Main scoring kernel: blockIdx.x = element chunk, blockIdx.y = candidate group.
__global__ void __launch_bounds__(TPB, 2) k_score(const float* __restrict__ x, int n) {
    const int g     = blockIdx.y;
    const int chunk = blockIdx.x;

    float4 P[CPG];
    #pragma unroll
    for (int c = 0; c < CPG; c++) P[c] = g_params[g * CPG + c];
    float acc[CPG];
    #pragma unroll
    for (int c = 0; c < CPG; c++) acc[c] = 0.0f;

    const int chunk_elems = n / NCHUNK;           // 131072 (n divisible)
    const float4* x4 = (const float4*)(x + (size_t)chunk * chunk_elems);
    const int n4 = chunk_elems >> 2;              // 32768

    for (int i = threadIdx.x; i < n4; i += TPB) {
        float4 v = x4[i];
        float xs[4] = {v.x, v.y, v.z, v.w};
        #pragma unroll
        for (int e = 0; e < 4; e++) {
            float xe = xs[e];
            #pragma unroll
            for (int c = 0; c < CPG; c++) {
                float t  = __fmaf_rn(xe, P[c].y, MAGIC);   // round(x/s) via magic
                float r  = __fsub_rn(t, MAGIC);
                float rc = fminf(fmaxf(r, P[c].z), P[c].w); // clip(r, -zp, 15-zp)
                float er = __fmaf_rn(rc, P[c].x, -xe);      // xq - x
                acc[c]   = __fmaf_rn(er, er, acc[c]);
            }
        }
    }

    // Deterministic intra-block reduction.
    #pragma unroll
    for (int c = 0; c < CPG; c++)
        #pragma unroll
        for (int o = 16; o; o >>= 1)
            acc[c] += __shfl_down_sync(0xFFFFFFFFu, acc[c], o);

    __shared__ float s_acc[TPB / 32][CPG];
    int w = threadIdx.x >> 5;
    if ((threadIdx.x & 31) == 0) {
        #pragma unroll
        for (int c = 0; c < CPG; c++) s_acc[w][c] = acc[c];
    }
    __syncthreads();
    if (threadIdx.x < CPG) {
        float s = 0.0f;
        for (int ww = 0; ww < TPB / 32; ww++) s += s_acc[ww][threadIdx.x];
        g_partials[(g * NCHUNK + chunk) * CPG + threadIdx.x] = s;
    }
}

// Final reduction + sequential scan (mirrors jax.lax.scan semantics exactly).
__global__ void k_select(float* __restrict__ out, int n) {
    __shared__ float s_scores[NCAND];
    for (int k = threadIdx.x; k < NCAND; k += blockDim.x) {
        int gg = k / CPG, c = k % CPG;
        float s = 0.0f;
        for (int ch = 0; ch < NCHUNK; ch++)          // fixed order: deterministic
            s += g_partials[(gg * NCHUNK + ch) * CPG + c];
        s_scores[k] = s;
    }
    __syncthreads();
    if (threadIdx.x == 0) {
        float inv_n = 1.0f / (float)n;
        float best  = 1.0e10f;
        float bmin  = dec_ord(g_minmax_bits[0]);
        float bmax  = dec_ord(g_minmax_bits[1]);
        for (int ii = 0; ii < NI; ii++) {
            int   j  = 0;
            float sc = s_scores[ii * NZ];
            for (int c = 1; c < NZ; c++) {            // argmin, first occurrence
                float v = s_scores[ii * NZ + c];
                if (v < sc) { sc = v; j = c; }
            }
            float mean = sc * inv_n;
            if (mean < best) {
                best = mean;
                bmin = g_cand_mm[ii * NZ + j].x;
                bmax = g_cand_mm[ii * NZ + j].y;
            }
        }
        out[0] = bmin;
        out[1] = bmax;
    }
}

extern "C" void kernel_launch(void* const* d_in, const int* in_sizes, int n_in,
                              void* d_out, int out_size) {
    const float* x = (const float*)d_in[0];
    int n = in_sizes[0];          // 4194304, divisible by NCHUNK*4

    k_init<<<1, 1>>>();
    k_minmax<<<592, TPB>>>((const float4*)x, n / 4);
    k_params<<<(NCAND + TPB - 1) / TPB, TPB>>>();
    dim3 grid(NCHUNK, NGROUP);
    k_score<<<grid, TPB>>>(x, n);
    k_select<<<1, 512>>>((float*)d_out, n);
}

// round 5
// speedup vs baseline: 10.5621x; 10.5621x over previous
#include <cuda_runtime.h>
#include <math.h>

// MSEObserver via exact-moment CDF:
// E_c = Sum(x^2) + sum_m [(m*s)^2 * N_m - 2*(m*s) * S_m]  over 16 quant buckets.
// Bucket moments come from a 2^18-bin uniform CDF (integer count + 2^38 fixed-point sum,
// both built with deterministic integer atomics), prefix-summed, sampled at the bin
// boundary nearest each bucket edge. Selection scan mirrors the reference exactly.

#define NCAND   1600
#define NI      100
#define NZ      16
#define NB      (1 << 18)
#define NPART   256
#define TPB     256
#define SCALE_S      274877906944.0f          // 2^38 (exact pow2 scale for x)
#define INV_SCALE_S  (1.0 / 274877906944.0)
#define SCALE_SS     68719476736.0f           // 2^36 (scale for x^2)
#define INV_SCALE_SS (1.0 / 68719476736.0)

__device__ unsigned int       g_minmax_bits[2];
__device__ unsigned long long g_ss_fix;        // sum of x^2, fixed-point 2^36
__device__ unsigned int       g_cnt[NB];
__device__ unsigned long long g_sum[NB];       // signed fixed-point 2^38, stored as u64
__device__ unsigned int       g_pcnt[NB + 1];  // exclusive prefix of counts
__device__ long long          g_psum[NB + 1];  // exclusive prefix of sums
__device__ unsigned int       g_part_cnt[NPART];
__device__ long long          g_part_sum[NPART];
__device__ float4             g_params[NCAND]; // {scale, 1/scale, -zp, 15-zp}
__device__ float2             g_cand_mm[NCAND];
__device__ double             g_score[NCAND];  // V_c (score minus Sum(x^2))

__device__ __forceinline__ unsigned int enc_ord(float f) {
    unsigned int u = __float_as_uint(f);
    return (u & 0x80000000u) ? ~u : (u | 0x80000000u);
}
__device__ __forceinline__ float dec_ord(unsigned int u) {
    return (u & 0x80000000u) ? __uint_as_float(u ^ 0x80000000u)
                             : __uint_as_float(~u);
}

__global__ void k_init() {
    unsigned int i = blockIdx.x * blockDim.x + threadIdx.x;   // grid covers NB exactly
    g_cnt[i] = 0u;
    g_sum[i] = 0ull;
    if (i == 0) {
        g_minmax_bits[0] = 0xFFFFFFFFu;
        g_minmax_bits[1] = 0x00000000u;
        g_ss_fix = 0ull;
    }
}

__global__ void k_minmax(const float4* __restrict__ x4, int n4) {
    float mn =  3.402823466e+38f;
    float mx = -3.402823466e+38f;
    long long acc = 0;
    for (int i = blockIdx.x * blockDim.x + threadIdx.x; i < n4;
         i += gridDim.x * blockDim.x) {
        float4 v = x4[i];
        mn = fminf(mn, fminf(fminf(v.x, v.y), fminf(v.z, v.w)));
        mx = fmaxf(mx, fmaxf(fmaxf(v.x, v.y), fmaxf(v.z, v.w)));
        acc += __float2ll_rn(v.x * v.x * SCALE_SS);
        acc += __float2ll_rn(v.y * v.y * SCALE_SS);
        acc += __float2ll_rn(v.z * v.z * SCALE_SS);
        acc += __float2ll_rn(v.w * v.w * SCALE_SS);
    }
    #pragma unroll
    for (int o = 16; o; o >>= 1) {
        mn  = fminf(mn, __shfl_down_sync(0xFFFFFFFFu, mn, o));
        mx  = fmaxf(mx, __shfl_down_sync(0xFFFFFFFFu, mx, o));
        acc += __shfl_down_sync(0xFFFFFFFFu, acc, o);
    }
    __shared__ float smn[TPB / 32], smx[TPB / 32];
    __shared__ long long sac[TPB / 32];
    int w = threadIdx.x >> 5;
    if ((threadIdx.x & 31) == 0) { smn[w] = mn; smx[w] = mx; sac[w] = acc; }
    __syncthreads();
    if (threadIdx.x == 0) {
        for (int ww = 1; ww < TPB / 32; ww++) {
            mn = fminf(mn, smn[ww]); mx = fmaxf(mx, smx[ww]); acc += sac[ww];
        }
        atomicMin(&g_minmax_bits[0], enc_ord(mn));
        atomicMax(&g_minmax_bits[1], enc_ord(mx));
        atomicAdd(&g_ss_fix, (unsigned long long)acc);
    }
}

// Mirror the reference parameter math op-for-op in fp32 (no contraction).
__global__ void k_params() {
    int k = blockIdx.x * blockDim.x + threadIdx.x;
    if (k >= NCAND) return;
    float x_min = dec_ord(g_minmax_bits[0]);
    float x_max = dec_ord(g_minmax_bits[1]);
    float xrange = __fsub_rn(x_max, x_min);

    int ii = k / NZ;
    int z  = k % NZ;
    float fi = (float)(ii + 1);
    float zf = (float)z;

    float tmp_max   = __fmul_rn(__fdiv_rn(xrange, 100.0f), fi);
    float tmp_delta = __fdiv_rn(tmp_max, 15.0f);
    float p         = __fmul_rn(zf, tmp_delta);
    float new_min   = fmaxf(-p, x_min);
    float new_max   = fminf(__fsub_rn(tmp_max, p), x_max);
    float min_neg   = fminf(new_min, 0.0f);
    float max_pos   = fmaxf(new_max, 0.0f);
    float scale     = fmaxf(__fdiv_rn(__fsub_rn(max_pos, min_neg), 15.0f),
                            1.1920929e-07f);
    float zp = fminf(fmaxf(__fsub_rn(0.0f, rintf(__fdiv_rn(min_neg, scale))),
                           0.0f), 15.0f);

    g_params[k]  = make_float4(scale, __frcp_rn(scale), -zp, 15.0f - zp);
    g_cand_mm[k] = make_float2(new_min, new_max);
}

__global__ void k_build(const float4* __restrict__ x4, int n4) {
    float xmin = dec_ord(g_minmax_bits[0]);
    float xmax = dec_ord(g_minmax_bits[1]);
    float invw = (float)((double)NB / ((double)xmax - (double)xmin));
    for (int i = blockIdx.x * blockDim.x + threadIdx.x; i < n4;
         i += gridDim.x * blockDim.x) {
        float4 v = x4[i];
        float xs[4] = {v.x, v.y, v.z, v.w};
        #pragma unroll
        for (int e = 0; e < 4; e++) {
            float xe = xs[e];
            int b = (int)((xe - xmin) * invw);
            b = b < 0 ? 0 : (b > NB - 1 ? NB - 1 : b);
            atomicAdd(&g_cnt[b], 1u);
            long long fx = __float2ll_rn(xe * SCALE_S);   // exact pow2 scaling
            atomicAdd(&g_sum[b], (unsigned long long)fx);
        }
    }
}

__global__ void k_scan1() {
    __shared__ unsigned int sc[TPB];
    __shared__ long long    ss[TPB];
    int t = threadIdx.x;
    int base = blockIdx.x * (NB / NPART) + t * 4;
    unsigned int c = 0; long long s = 0;
    #pragma unroll
    for (int i = 0; i < 4; i++) {
        c += g_cnt[base + i];
        s += (long long)g_sum[base + i];
    }
    sc[t] = c; ss[t] = s;
    __syncthreads();
    for (int off = TPB / 2; off; off >>= 1) {
        if (t < off) { sc[t] += sc[t + off]; ss[t] += ss[t + off]; }
        __syncthreads();
    }
    if (t == 0) { g_part_cnt[blockIdx.x] = sc[0]; g_part_sum[blockIdx.x] = ss[0]; }
}

__global__ void k_scan2() {
    unsigned int rc = 0; long long rs = 0;
    for (int i = 0; i < NPART; i++) {
        unsigned int tc = g_part_cnt[i]; long long ts = g_part_sum[i];
        g_part_cnt[i] = rc; g_part_sum[i] = rs;
        rc += tc; rs += ts;
    }
}

__global__ void k_scan3() {
    __shared__ unsigned int sc[TPB];
    __shared__ long long    ss[TPB];
    int t = threadIdx.x;
    int base = blockIdx.x * (NB / NPART) + t * 4;
    unsigned int c[4]; long long s[4];
    unsigned int cl = 0; long long sl = 0;
    #pragma unroll
    for (int i = 0; i < 4; i++) {
        c[i] = g_cnt[base + i];
        s[i] = (long long)g_sum[base + i];
        cl += c[i]; sl += s[i];
    }
    sc[t] = cl; ss[t] = sl;
    __syncthreads();
    for (int off = 1; off < TPB; off <<= 1) {          // Hillis-Steele inclusive
        unsigned int cv = 0; long long sv = 0;
        if (t >= off) { cv = sc[t - off]; sv = ss[t - off]; }
        __syncthreads();
        if (t >= off) { sc[t] += cv; ss[t] += sv; }
        __syncthreads();
    }
    unsigned int runc = g_part_cnt[blockIdx.x] + (t ? sc[t - 1] : 0u);
    long long    runs = g_part_sum[blockIdx.x] + (t ? ss[t - 1] : 0ll);
    #pragma unroll
    for (int i = 0; i < 4; i++) {
        g_pcnt[base + i] = runc;
        g_psum[base + i] = runs;
        runc += c[i]; runs += s[i];
    }
    if (blockIdx.x == NPART - 1 && t == TPB - 1) {
        g_pcnt[NB] = runc;          // total N
        g_psum[NB] = runs;          // total fixed-point sum
    }
}

__global__ void k_eval() {
    int k = blockIdx.x * blockDim.x + threadIdx.x;
    if (k >= NCAND) return;
    float4 P = g_params[k];
    double s    = (double)P.x;
    double lo   = (double)P.z;                 // -zp
    double xmin = (double)dec_ord(g_minmax_bits[0]);
    double xmax = (double)dec_ord(g_minmax_bits[1]);
    double invw = (double)NB / (xmax - xmin);
    unsigned int Ntot = g_pcnt[NB];
    long long    Stot = g_psum[NB];

    double V = 0.0;
    unsigned int prevC = 0u; long long prevS = 0ll;
    #pragma unroll
    for (int j = 0; j < 16; j++) {
        double m = lo + (double)j;
        unsigned int C; long long S;
        if (j < 15) {
            double e   = s * (m + 0.5);
            double pos = (e - xmin) * invw;
            int b = __double2int_rn(pos);
            b = b < 0 ? 0 : (b > NB ? NB : b);
            C = g_pcnt[b]; S = g_psum[b];
        } else { C = Ntot; S = Stot; }
        double dC = (double)(C - prevC);
        double dS = (double)(S - prevS) * INV_SCALE_S;
        double q  = m * s;
        V += q * (q * dC - 2.0 * dS);
        prevC = C; prevS = S;
    }
    g_score[k] = V;
}

// Final selection: mirrors jax.lax.scan semantics (fp32 score comparisons).
__global__ void k_select(float* __restrict__ out, int n) {
    __shared__ float s_scores[NCAND];
    double ss = (double)(long long)g_ss_fix * INV_SCALE_SS;
    double inv_n = 1.0 / (double)n;
    for (int k = threadIdx.x; k < NCAND; k += blockDim.x)
        s_scores[k] = (float)((ss + g_score[k]) * inv_n);
    __syncthreads();
    if (threadIdx.x == 0) {
        float best = 1.0e10f;
        float bmin = dec_ord(g_minmax_bits[0]);
        float bmax = dec_ord(g_minmax_bits[1]);
        for (int ii = 0; ii < NI; ii++) {
            int   j  = 0;
            float sc = s_scores[ii * NZ];
            for (int c = 1; c < NZ; c++) {
                float v = s_scores[ii * NZ + c];
                if (v < sc) { sc = v; j = c; }
            }
            if (sc < best) {
                best = sc;
                bmin = g_cand_mm[ii * NZ + j].x;
                bmax = g_cand_mm[ii * NZ + j].y;
            }
        }
        out[0] = bmin;
        out[1] = bmax;
    }
}

extern "C" void kernel_launch(void* const* d_in, const int* in_sizes, int n_in,
                              void* d_out, int out_size) {
    const float* x = (const float*)d_in[0];
    int n = in_sizes[0];                      // 4194304

    k_init<<<NB / TPB, TPB>>>();
    k_minmax<<<592, TPB>>>((const float4*)x, n / 4);
    k_params<<<(NCAND + TPB - 1) / TPB, TPB>>>();
    k_build<<<1184, TPB>>>((const float4*)x, n / 4);
    k_scan1<<<NPART, TPB>>>();
    k_scan2<<<1, 1>>>();
    k_scan3<<<NPART, TPB>>>();
    k_eval<<<200, 8>>>();
    k_select<<<1, TPB>>>((float*)d_out, n);
}